// round 6
// baseline (speedup 1.0000x reference)
#include <cuda_runtime.h>
#include <cstdint>

// Bidirectional tanh-Elman RNN, B=32, S=2048, D=H=256, fp32.
//
// Phase 1 (xp_kernel): xp[dir] = x @ Wx_dir + b_dir  -> 128MB device scratch.
// Phase 2 (rnn_kernel): 64 clusters of 2 CTAs; cluster = one (dir, batch).
//   Each CTA holds half of Wh (its 128 output columns) in REGISTERS
//   (128 regs/thread), h vector lives in smem, halves exchanged each step
//   via DSMEM st.async + mbarrier. No device-wide barrier, no L2 ping-pong.

#define S_SZ 2048
#define H_SZ 256
#define B_SZ 32

__device__ float g_xp[2u * 65536u * 256u];   // [dir][b*S + s][j]  128 MB scratch

// ---------------------------------------------------------------------------
// Phase 1: input projection GEMM (fp32), rows = flattened (b, s)
// ---------------------------------------------------------------------------
#define XP_ROWS 64
#define XP_KC   64
#define XP_SMEM_FLOATS (XP_KC * 256 + XP_KC * 64)   // sW + sXT = 20480 floats

__global__ __launch_bounds__(256, 2) void xp_kernel(
    const float* __restrict__ x,
    const float* __restrict__ Wx_f, const float* __restrict__ b_f,
    const float* __restrict__ Wx_b, const float* __restrict__ b_b)
{
    extern __shared__ float sm[];
    float* sW  = sm;                 // [64][256]  sW[ii*256 + j]
    float* sXT = sm + XP_KC * 256;   // [64][64]   sXT[ii*64 + r]

    const int dir  = blockIdx.y;
    const int row0 = blockIdx.x * XP_ROWS;
    const float* W    = dir ? Wx_b : Wx_f;
    const float* bias = dir ? b_b  : b_f;
    const int t = threadIdx.x;
    const int j = t;                 // output column

    float acc[XP_ROWS];
    const float bv = bias[j];
    #pragma unroll
    for (int r = 0; r < XP_ROWS; ++r) acc[r] = bv;

    for (int i0 = 0; i0 < H_SZ; i0 += XP_KC) {
        // stage W chunk [64 i][256 j] (coalesced)
        for (int idx = t; idx < XP_KC * 256; idx += 256)
            sW[idx] = W[(i0 + (idx >> 8)) * H_SZ + (idx & 255)];
        // stage x chunk transposed: thread t handles row r = t>>2, i-range (t&3)*16
        {
            int r  = t >> 2;
            int iq = (t & 3) * 16;
            const float* xr = x + (size_t)(row0 + r) * H_SZ + i0 + iq;
            #pragma unroll
            for (int k = 0; k < 4; ++k) {
                float4 v = *(const float4*)(xr + k * 4);
                sXT[(iq + k*4 + 0) * 64 + r] = v.x;
                sXT[(iq + k*4 + 1) * 64 + r] = v.y;
                sXT[(iq + k*4 + 2) * 64 + r] = v.z;
                sXT[(iq + k*4 + 3) * 64 + r] = v.w;
            }
        }
        __syncthreads();
        for (int ii = 0; ii < XP_KC; ++ii) {
            float wv = sW[ii * 256 + j];
            const float4* xv = (const float4*)(sXT + ii * 64);
            #pragma unroll
            for (int r4 = 0; r4 < 16; ++r4) {
                float4 v = xv[r4];           // broadcast
                acc[r4*4+0] = fmaf(v.x, wv, acc[r4*4+0]);
                acc[r4*4+1] = fmaf(v.y, wv, acc[r4*4+1]);
                acc[r4*4+2] = fmaf(v.z, wv, acc[r4*4+2]);
                acc[r4*4+3] = fmaf(v.w, wv, acc[r4*4+3]);
            }
        }
        __syncthreads();
    }
    float* dst = g_xp + ((size_t)dir * 65536u + row0) * 256 + j;
    #pragma unroll
    for (int r = 0; r < XP_ROWS; ++r) dst[(size_t)r * 256] = acc[r];
}

// ---------------------------------------------------------------------------
// Phase 2: recurrence. grid = 128 CTAs (clusters of 2), 256 threads.
// cluster c = dir*32 + b; rank = j-half. thread: kh = t>>7 (k-half), jl = t&127.
// ---------------------------------------------------------------------------
__device__ __forceinline__ uint32_t smem_u32(const void* p) {
    uint32_t a;
    asm("{ .reg .u64 tmp; cvta.to.shared.u64 tmp, %1; cvt.u32.u64 %0, tmp; }"
        : "=r"(a) : "l"(p));
    return a;
}

__global__ __launch_bounds__(256, 1) __cluster_dims__(2, 1, 1)
void rnn_kernel(const float* __restrict__ Wh_f,
                const float* __restrict__ Wh_b,
                float* __restrict__ out)
{
    __shared__ float sH[2][H_SZ];          // full h vector, double-buffered
    __shared__ float sRed[128];            // k-partials from kh=1
    __shared__ __align__(8) unsigned long long sBar;

    const int t     = threadIdx.x;
    const int rank  = blockIdx.x & 1;      // j-half owned by this CTA
    const int c     = blockIdx.x >> 1;
    const int dir   = c >> 5;
    const int b     = c & 31;
    const int kh    = t >> 7;
    const int jl    = t & 127;
    const int jglob = rank * 128 + jl;

    const float* Wh = dir ? Wh_b : Wh_f;

    // Wh[:, jglob] in registers: w[ii] = Wh[kh*128+ii][jglob]
    float w[128];
    #pragma unroll
    for (int ii = 0; ii < 128; ++ii)
        w[ii] = Wh[(kh * 128 + ii) * H_SZ + jglob];

    // init h = 0, init mbarrier (1 arrival/generation: our own expect_tx)
    sH[0][t] = 0.0f;
    const uint32_t barLocal = smem_u32(&sBar);
    const uint32_t shBase   = smem_u32(&sH[0][0]);
    if (t == 0)
        asm volatile("mbarrier.init.shared.b64 [%0], %1;" :: "r"(barLocal), "r"(1) : "memory");
    __syncthreads();
    asm volatile("barrier.cluster.arrive.aligned;" ::: "memory");
    asm volatile("barrier.cluster.wait.aligned;"   ::: "memory");

    uint32_t peerBar, peerSh;
    {
        uint32_t pr = rank ^ 1;
        asm("mapa.shared::cluster.u32 %0, %1, %2;" : "=r"(peerBar) : "r"(barLocal), "r"(pr));
        asm("mapa.shared::cluster.u32 %0, %1, %2;" : "=r"(peerSh)  : "r"(shBase),   "r"(pr));
    }

    const float* xp_base  = g_xp + ((size_t)dir * 65536u + (size_t)b * S_SZ) * 256 + jglob;
    float*       out_base = out + (size_t)b * S_SZ * 512 + dir * 256 + jglob;

    int sx = dir ? (S_SZ - 1) : 0;
    const int sstep = dir ? -1 : 1;
    float xpv = (t < 128) ? __ldg(xp_base + (size_t)sx * 256) : 0.0f;

    for (int s = 0; s < S_SZ; ++s) {
        // declare expected incoming bytes for this generation (peer's 128 floats)
        if (t == 0 && s + 1 < S_SZ)
            asm volatile("mbarrier.arrive.expect_tx.shared.b64 _, [%0], %1;"
                         :: "r"(barLocal), "r"(512) : "memory");

        // prefetch next step's xp
        float xpn = 0.0f;
        if (t < 128 && s + 1 < S_SZ)
            xpn = __ldg(xp_base + (size_t)(sx + sstep) * 256);

        // partial GEMV over this thread's k-half (weights in registers,
        // h broadcast from smem)
        const float* hb = sH[s & 1] + (kh << 7);
        float a0 = 0.f, a1 = 0.f, a2 = 0.f, a3 = 0.f;
        #pragma unroll
        for (int q = 0; q < 32; ++q) {
            float4 hv = *(const float4*)(hb + (q << 2));   // broadcast LDS.128
            a0 = fmaf(hv.x, w[4*q+0], a0);
            a1 = fmaf(hv.y, w[4*q+1], a1);
            a2 = fmaf(hv.z, w[4*q+2], a2);
            a3 = fmaf(hv.w, w[4*q+3], a3);
        }
        float acc = (a0 + a1) + (a2 + a3);

        if (kh) sRed[jl] = acc;
        __syncthreads();

        if (t < 128) {
            float hnew = tanhf(acc + sRed[jl] + xpv);
            int nb = (s + 1) & 1;
            sH[nb][jglob] = hnew;                           // local copy
            out_base[(size_t)sx * 512] = hnew;              // output (coalesced)
            if (s + 1 < S_SZ) {
                // remote copy into peer's h buffer; tx credited to peer's bar
                uint32_t dst = peerSh + (uint32_t)(nb * 256 + jglob) * 4u;
                asm volatile(
                    "st.async.shared::cluster.mbarrier::complete_tx::bytes.u32 [%0], %1, [%2];"
                    :: "r"(dst), "r"(__float_as_uint(hnew)), "r"(peerBar) : "memory");
            }
        }
        xpv = xpn;
        __syncthreads();   // local sH[nb] writes visible; sRed safe for reuse

        if (s + 1 < S_SZ) {
            // wait for peer's half of h_next (parity = s & 1)
            uint32_t parity = (uint32_t)(s & 1);
            asm volatile(
                "{\n\t.reg .pred P;\n\t"
                "WL_%=:\n\t"
                "mbarrier.try_wait.parity.acquire.cluster.shared::cta.b64 P, [%0], %1, 0x989680;\n\t"
                "@!P bra WL_%=;\n\t}"
                :: "r"(barLocal), "r"(parity) : "memory");
        }
        sx += sstep;
    }
}

// ---------------------------------------------------------------------------
extern "C" void kernel_launch(void* const* d_in, const int* in_sizes, int n_in,
                              void* d_out, int out_size)
{
    const float* x    = (const float*)d_in[0];
    const float* Wx_f = (const float*)d_in[1];
    const float* Wh_f = (const float*)d_in[2];
    const float* b_f  = (const float*)d_in[3];
    const float* Wx_b = (const float*)d_in[4];
    const float* Wh_b = (const float*)d_in[5];
    const float* b_b  = (const float*)d_in[6];
    float* out = (float*)d_out;

    cudaFuncSetAttribute(xp_kernel, cudaFuncAttributeMaxDynamicSharedMemorySize,
                         XP_SMEM_FLOATS * 4);

    dim3 xpgrid(65536 / XP_ROWS, 2);
    xp_kernel<<<xpgrid, 256, XP_SMEM_FLOATS * 4>>>(x, Wx_f, b_f, Wx_b, b_b);
    rnn_kernel<<<128, 256>>>(Wh_f, Wh_b, out);
}

// round 7
// speedup vs baseline: 1.0007x; 1.0007x over previous
#include <cuda_runtime.h>
#include <cstdint>

// Bidirectional tanh-Elman RNN, B=32, S=2048, D=H=256, fp32.
//
// Phase 1 (xp_kernel): xp[dir] = x @ Wx_dir + b_dir  -> 128MB device scratch.
// Phase 2 (rnn_kernel): 64 clusters of 2 CTAs; cluster = one (dir, batch).
//   Each CTA holds half of Wh (its 128 output columns) in REGISTERS
//   (128 regs/thread), h vector lives in smem, halves exchanged each step
//   via DSMEM st.async + mbarrier. No device-wide barrier, no L2 ping-pong.

#define S_SZ 2048
#define H_SZ 256
#define B_SZ 32

__device__ float g_xp[2u * 65536u * 256u];   // [dir][b*S + s][j]  128 MB scratch

// ---------------------------------------------------------------------------
// Phase 1: input projection GEMM (fp32), rows = flattened (b, s)
// ---------------------------------------------------------------------------
#define XP_ROWS 64
#define XP_KC   64
#define XP_SMEM_FLOATS (XP_KC * 256 + XP_KC * 64)   // sW + sXT = 20480 floats

__global__ __launch_bounds__(256, 2) void xp_kernel(
    const float* __restrict__ x,
    const float* __restrict__ Wx_f, const float* __restrict__ b_f,
    const float* __restrict__ Wx_b, const float* __restrict__ b_b)
{
    extern __shared__ float sm[];
    float* sW  = sm;                 // [64][256]  sW[ii*256 + j]
    float* sXT = sm + XP_KC * 256;   // [64][64]   sXT[ii*64 + r]

    const int dir  = blockIdx.y;
    const int row0 = blockIdx.x * XP_ROWS;
    const float* W    = dir ? Wx_b : Wx_f;
    const float* bias = dir ? b_b  : b_f;
    const int t = threadIdx.x;
    const int j = t;                 // output column

    float acc[XP_ROWS];
    const float bv = bias[j];
    #pragma unroll
    for (int r = 0; r < XP_ROWS; ++r) acc[r] = bv;

    for (int i0 = 0; i0 < H_SZ; i0 += XP_KC) {
        // stage W chunk [64 i][256 j] (coalesced)
        for (int idx = t; idx < XP_KC * 256; idx += 256)
            sW[idx] = W[(i0 + (idx >> 8)) * H_SZ + (idx & 255)];
        // stage x chunk transposed: thread t handles row r = t>>2, i-range (t&3)*16
        {
            int r  = t >> 2;
            int iq = (t & 3) * 16;
            const float* xr = x + (size_t)(row0 + r) * H_SZ + i0 + iq;
            #pragma unroll
            for (int k = 0; k < 4; ++k) {
                float4 v = *(const float4*)(xr + k * 4);
                sXT[(iq + k*4 + 0) * 64 + r] = v.x;
                sXT[(iq + k*4 + 1) * 64 + r] = v.y;
                sXT[(iq + k*4 + 2) * 64 + r] = v.z;
                sXT[(iq + k*4 + 3) * 64 + r] = v.w;
            }
        }
        __syncthreads();
        for (int ii = 0; ii < XP_KC; ++ii) {
            float wv = sW[ii * 256 + j];
            const float4* xv = (const float4*)(sXT + ii * 64);
            #pragma unroll
            for (int r4 = 0; r4 < 16; ++r4) {
                float4 v = xv[r4];           // broadcast
                acc[r4*4+0] = fmaf(v.x, wv, acc[r4*4+0]);
                acc[r4*4+1] = fmaf(v.y, wv, acc[r4*4+1]);
                acc[r4*4+2] = fmaf(v.z, wv, acc[r4*4+2]);
                acc[r4*4+3] = fmaf(v.w, wv, acc[r4*4+3]);
            }
        }
        __syncthreads();
    }
    float* dst = g_xp + ((size_t)dir * 65536u + row0) * 256 + j;
    #pragma unroll
    for (int r = 0; r < XP_ROWS; ++r) dst[(size_t)r * 256] = acc[r];
}

// ---------------------------------------------------------------------------
// Phase 2: recurrence. grid = 128 CTAs (clusters of 2), 256 threads.
// cluster c = dir*32 + b; rank = j-half. thread: kh = t>>7 (k-half), jl = t&127.
// ---------------------------------------------------------------------------
__device__ __forceinline__ uint32_t smem_u32(const void* p) {
    uint32_t a;
    asm("{ .reg .u64 tmp; cvta.to.shared.u64 tmp, %1; cvt.u32.u64 %0, tmp; }"
        : "=r"(a) : "l"(p));
    return a;
}

__global__ __launch_bounds__(256, 1) __cluster_dims__(2, 1, 1)
void rnn_kernel(const float* __restrict__ Wh_f,
                const float* __restrict__ Wh_b,
                float* __restrict__ out)
{
    __shared__ float sH[2][H_SZ];          // full h vector, double-buffered
    __shared__ float sRed[128];            // k-partials from kh=1
    __shared__ __align__(8) unsigned long long sBar;

    const int t     = threadIdx.x;
    const int rank  = blockIdx.x & 1;      // j-half owned by this CTA
    const int c     = blockIdx.x >> 1;
    const int dir   = c >> 5;
    const int b     = c & 31;
    const int kh    = t >> 7;
    const int jl    = t & 127;
    const int jglob = rank * 128 + jl;

    const float* Wh = dir ? Wh_b : Wh_f;

    // Wh[:, jglob] in registers: w[ii] = Wh[kh*128+ii][jglob]
    float w[128];
    #pragma unroll
    for (int ii = 0; ii < 128; ++ii)
        w[ii] = Wh[(kh * 128 + ii) * H_SZ + jglob];

    // init h = 0, init mbarrier (1 arrival/generation: our own expect_tx)
    sH[0][t] = 0.0f;
    const uint32_t barLocal = smem_u32(&sBar);
    const uint32_t shBase   = smem_u32(&sH[0][0]);
    if (t == 0)
        asm volatile("mbarrier.init.shared.b64 [%0], %1;" :: "r"(barLocal), "r"(1) : "memory");
    __syncthreads();
    asm volatile("barrier.cluster.arrive.aligned;" ::: "memory");
    asm volatile("barrier.cluster.wait.aligned;"   ::: "memory");

    uint32_t peerBar, peerSh;
    {
        uint32_t pr = rank ^ 1;
        asm("mapa.shared::cluster.u32 %0, %1, %2;" : "=r"(peerBar) : "r"(barLocal), "r"(pr));
        asm("mapa.shared::cluster.u32 %0, %1, %2;" : "=r"(peerSh)  : "r"(shBase),   "r"(pr));
    }

    const float* xp_base  = g_xp + ((size_t)dir * 65536u + (size_t)b * S_SZ) * 256 + jglob;
    float*       out_base = out + (size_t)b * S_SZ * 512 + dir * 256 + jglob;

    int sx = dir ? (S_SZ - 1) : 0;
    const int sstep = dir ? -1 : 1;
    float xpv = (t < 128) ? __ldg(xp_base + (size_t)sx * 256) : 0.0f;

    for (int s = 0; s < S_SZ; ++s) {
        // declare expected incoming bytes for this generation (peer's 128 floats)
        if (t == 0 && s + 1 < S_SZ)
            asm volatile("mbarrier.arrive.expect_tx.shared.b64 _, [%0], %1;"
                         :: "r"(barLocal), "r"(512) : "memory");

        // prefetch next step's xp
        float xpn = 0.0f;
        if (t < 128 && s + 1 < S_SZ)
            xpn = __ldg(xp_base + (size_t)(sx + sstep) * 256);

        // partial GEMV over this thread's k-half (weights in registers,
        // h broadcast from smem)
        const float* hb = sH[s & 1] + (kh << 7);
        float a0 = 0.f, a1 = 0.f, a2 = 0.f, a3 = 0.f;
        #pragma unroll
        for (int q = 0; q < 32; ++q) {
            float4 hv = *(const float4*)(hb + (q << 2));   // broadcast LDS.128
            a0 = fmaf(hv.x, w[4*q+0], a0);
            a1 = fmaf(hv.y, w[4*q+1], a1);
            a2 = fmaf(hv.z, w[4*q+2], a2);
            a3 = fmaf(hv.w, w[4*q+3], a3);
        }
        float acc = (a0 + a1) + (a2 + a3);

        if (kh) sRed[jl] = acc;
        __syncthreads();

        if (t < 128) {
            float hnew = tanhf(acc + sRed[jl] + xpv);
            int nb = (s + 1) & 1;
            sH[nb][jglob] = hnew;                           // local copy
            out_base[(size_t)sx * 512] = hnew;              // output (coalesced)
            if (s + 1 < S_SZ) {
                // remote copy into peer's h buffer; tx credited to peer's bar
                uint32_t dst = peerSh + (uint32_t)(nb * 256 + jglob) * 4u;
                asm volatile(
                    "st.async.shared::cluster.mbarrier::complete_tx::bytes.u32 [%0], %1, [%2];"
                    :: "r"(dst), "r"(__float_as_uint(hnew)), "r"(peerBar) : "memory");
            }
        }
        xpv = xpn;
        __syncthreads();   // local sH[nb] writes visible; sRed safe for reuse

        if (s + 1 < S_SZ) {
            // wait for peer's half of h_next (parity = s & 1)
            uint32_t parity = (uint32_t)(s & 1);
            asm volatile(
                "{\n\t.reg .pred P;\n\t"
                "WL_%=:\n\t"
                "mbarrier.try_wait.parity.acquire.cluster.shared::cta.b64 P, [%0], %1, 0x989680;\n\t"
                "@!P bra WL_%=;\n\t}"
                :: "r"(barLocal), "r"(parity) : "memory");
        }
        sx += sstep;
    }
}

// ---------------------------------------------------------------------------
extern "C" void kernel_launch(void* const* d_in, const int* in_sizes, int n_in,
                              void* d_out, int out_size)
{
    const float* x    = (const float*)d_in[0];
    const float* Wx_f = (const float*)d_in[1];
    const float* Wh_f = (const float*)d_in[2];
    const float* b_f  = (const float*)d_in[3];
    const float* Wx_b = (const float*)d_in[4];
    const float* Wh_b = (const float*)d_in[5];
    const float* b_b  = (const float*)d_in[6];
    float* out = (float*)d_out;

    cudaFuncSetAttribute(xp_kernel, cudaFuncAttributeMaxDynamicSharedMemorySize,
                         XP_SMEM_FLOATS * 4);

    dim3 xpgrid(65536 / XP_ROWS, 2);
    xp_kernel<<<xpgrid, 256, XP_SMEM_FLOATS * 4>>>(x, Wx_f, b_f, Wx_b, b_b);
    rnn_kernel<<<128, 256>>>(Wh_f, Wh_b, out);
}

// round 12
// speedup vs baseline: 1.0226x; 1.0219x over previous
#include <cuda_runtime.h>
#include <cstdint>

// Bidirectional tanh-Elman RNN, B=32, S=2048, D=H=256, fp32.
//
// Phase 1 (xp_kernel): xp[dir] = x @ Wx_dir + b_dir  -> 128MB device scratch.
// Phase 2 (rnn_kernel): 64 clusters of 2 CTAs; cluster = one (dir, batch).
//   Wh columns in registers, h in smem, halves exchanged via DSMEM st.async
//   + mbarrier.  Control flow/synchronization identical to the proven R7
//   version; compute uses packed fma.rn.f32x2 (2 FMA per issue slot) for a
//   bit-identical result at half the FFMA issue count.

#define S_SZ 2048
#define H_SZ 256
#define B_SZ 32

__device__ float g_xp[2u * 65536u * 256u];   // [dir][b*S + s][j]  128 MB scratch

__device__ __forceinline__ unsigned long long pack2(float a, float b) {
    unsigned long long r;
    asm("mov.b64 %0, {%1, %2};" : "=l"(r)
        : "r"(__float_as_uint(a)), "r"(__float_as_uint(b)));
    return r;
}
__device__ __forceinline__ void unpack2(unsigned long long p, float& a, float& b) {
    unsigned int lo, hi;
    asm("mov.b64 {%0, %1}, %2;" : "=r"(lo), "=r"(hi) : "l"(p));
    a = __uint_as_float(lo);
    b = __uint_as_float(hi);
}
#define FMA2(acc, a, b) \
    asm("fma.rn.f32x2 %0, %1, %2, %0;" : "+l"(acc) : "l"(a), "l"(b))

// ---------------------------------------------------------------------------
// Phase 1: input projection GEMM (fp32, FFMA2), rows = flattened (b, s)
// ---------------------------------------------------------------------------
#define XP_ROWS 64
#define XP_KC   64
#define XP_SMEM_FLOATS (XP_KC * 256 + XP_KC * 64)   // sW + sXT = 20480 floats

__global__ __launch_bounds__(256, 2) void xp_kernel(
    const float* __restrict__ x,
    const float* __restrict__ Wx_f, const float* __restrict__ b_f,
    const float* __restrict__ Wx_b, const float* __restrict__ b_b)
{
    extern __shared__ float sm[];
    float* sW  = sm;                 // [64][256]  sW[ii*256 + j]
    float* sXT = sm + XP_KC * 256;   // [64][64]   sXT[ii*64 + r]  (16B aligned)

    const int dir  = blockIdx.y;
    const int row0 = blockIdx.x * XP_ROWS;
    const float* W    = dir ? Wx_b : Wx_f;
    const float* bias = dir ? b_b  : b_f;
    const int t = threadIdx.x;
    const int j = t;                 // output column

    // 32 packed accumulators; acc2[k] = rows (2k, 2k+1)
    unsigned long long acc2[XP_ROWS / 2];
    {
        const float bv = bias[j];
        unsigned long long bp = pack2(bv, bv);
        #pragma unroll
        for (int k = 0; k < XP_ROWS / 2; ++k) acc2[k] = bp;
    }

    for (int i0 = 0; i0 < H_SZ; i0 += XP_KC) {
        for (int idx = t; idx < XP_KC * 256; idx += 256)
            sW[idx] = W[(i0 + (idx >> 8)) * H_SZ + (idx & 255)];
        {
            int r  = t >> 2;
            int iq = (t & 3) * 16;
            const float* xr = x + (size_t)(row0 + r) * H_SZ + i0 + iq;
            #pragma unroll
            for (int k = 0; k < 4; ++k) {
                float4 v = *(const float4*)(xr + k * 4);
                sXT[(iq + k*4 + 0) * 64 + r] = v.x;
                sXT[(iq + k*4 + 1) * 64 + r] = v.y;
                sXT[(iq + k*4 + 2) * 64 + r] = v.z;
                sXT[(iq + k*4 + 3) * 64 + r] = v.w;
            }
        }
        __syncthreads();
        for (int ii = 0; ii < XP_KC; ++ii) {
            unsigned int wu = __float_as_uint(sW[ii * 256 + j]);
            unsigned long long wv2;
            asm("mov.b64 %0, {%1, %1};" : "=l"(wv2) : "r"(wu));
            const ulonglong2* xv = (const ulonglong2*)(sXT + ii * 64);
            #pragma unroll
            for (int r2 = 0; r2 < 16; ++r2) {
                ulonglong2 v = xv[r2];            // rows 4r2..4r2+3 (broadcast)
                FMA2(acc2[2*r2 + 0], v.x, wv2);
                FMA2(acc2[2*r2 + 1], v.y, wv2);
            }
        }
        __syncthreads();
    }
    float* dst = g_xp + ((size_t)dir * 65536u + row0) * 256 + j;
    #pragma unroll
    for (int k = 0; k < XP_ROWS / 2; ++k) {
        float a, b;
        unpack2(acc2[k], a, b);
        dst[(size_t)(2*k + 0) * 256] = a;
        dst[(size_t)(2*k + 1) * 256] = b;
    }
}

// ---------------------------------------------------------------------------
// Phase 2: recurrence (R7 protocol verbatim; FFMA2 dot).
// ---------------------------------------------------------------------------
__device__ __forceinline__ uint32_t smem_u32(const void* p) {
    uint32_t a;
    asm("{ .reg .u64 tmp; cvta.to.shared.u64 tmp, %1; cvt.u32.u64 %0, tmp; }"
        : "=r"(a) : "l"(p));
    return a;
}

__global__ __launch_bounds__(256, 1) __cluster_dims__(2, 1, 1)
void rnn_kernel(const float* __restrict__ Wh_f,
                const float* __restrict__ Wh_b,
                float* __restrict__ out)
{
    __shared__ __align__(16) float sH[2][H_SZ];   // full h vector, double-buffered
    __shared__ float sRed[128];                   // k-partials from kh=1
    __shared__ __align__(8) unsigned long long sBar;

    const int t     = threadIdx.x;
    const int rank  = blockIdx.x & 1;      // j-half owned by this CTA
    const int c     = blockIdx.x >> 1;
    const int dir   = c >> 5;
    const int b     = c & 31;
    const int kh    = t >> 7;
    const int jl    = t & 127;
    const int jglob = rank * 128 + jl;

    const float* Wh = dir ? Wh_b : Wh_f;

    // Wh[:, jglob] packed in register pairs: w2[i] = (Wh[kh*128+2i], Wh[kh*128+2i+1])
    unsigned long long w2[64];
    #pragma unroll
    for (int ii = 0; ii < 64; ++ii)
        w2[ii] = pack2(Wh[(kh * 128 + 2*ii + 0) * H_SZ + jglob],
                       Wh[(kh * 128 + 2*ii + 1) * H_SZ + jglob]);

    sH[0][t] = 0.0f;
    const uint32_t barLocal = smem_u32(&sBar);
    const uint32_t shBase   = smem_u32(&sH[0][0]);
    if (t == 0)
        asm volatile("mbarrier.init.shared.b64 [%0], %1;" :: "r"(barLocal), "r"(1) : "memory");
    __syncthreads();
    asm volatile("barrier.cluster.arrive.aligned;" ::: "memory");
    asm volatile("barrier.cluster.wait.aligned;"   ::: "memory");

    uint32_t peerBar, peerSh;
    {
        uint32_t pr = rank ^ 1;
        asm("mapa.shared::cluster.u32 %0, %1, %2;" : "=r"(peerBar) : "r"(barLocal), "r"(pr));
        asm("mapa.shared::cluster.u32 %0, %1, %2;" : "=r"(peerSh)  : "r"(shBase),   "r"(pr));
    }

    const float* xp_base  = g_xp + ((size_t)dir * 65536u + (size_t)b * S_SZ) * 256 + jglob;
    float*       out_base = out + (size_t)b * S_SZ * 512 + dir * 256 + jglob;

    int sx = dir ? (S_SZ - 1) : 0;
    const int sstep = dir ? -1 : 1;
    float xpv = (t < 128) ? __ldg(xp_base + (size_t)sx * 256) : 0.0f;

    for (int s = 0; s < S_SZ; ++s) {
        // one expect_tx per generation; safe: phase s-1 is complete for every
        // thread (all threads passed the try_wait + __syncthreads below)
        if (t == 0 && s + 1 < S_SZ)
            asm volatile("mbarrier.arrive.expect_tx.shared.b64 _, [%0], %1;"
                         :: "r"(barLocal), "r"(512) : "memory");

        // prefetch next step's xp
        float xpn = 0.0f;
        if (t < 128 && s + 1 < S_SZ)
            xpn = __ldg(xp_base + (size_t)(sx + sstep) * 256);

        // partial GEMV over this thread's k-half: packed f32x2 FMA
        // (identical summation tree to scalar version -> bit-identical)
        const float* hb = sH[s & 1] + (kh << 7);
        unsigned long long p0 = 0ull, p1 = 0ull;   // (0.f,0.f) packed
        #pragma unroll
        for (int q = 0; q < 32; ++q) {
            ulonglong2 hv = *(const ulonglong2*)(hb + (q << 2));  // broadcast
            FMA2(p0, hv.x, w2[2*q + 0]);
            FMA2(p1, hv.y, w2[2*q + 1]);
        }
        float a0, a1, a2, a3;
        unpack2(p0, a0, a1);
        unpack2(p1, a2, a3);
        float acc = (a0 + a1) + (a2 + a3);

        if (kh) sRed[jl] = acc;
        __syncthreads();

        if (t < 128) {
            float hnew = tanhf(acc + sRed[jl] + xpv);
            int nb = (s + 1) & 1;
            sH[nb][jglob] = hnew;                      // local copy
            out_base[(size_t)sx * 512] = hnew;         // output (coalesced)
            if (s + 1 < S_SZ) {
                uint32_t dst = peerSh + (uint32_t)(nb * 256 + jglob) * 4u;
                asm volatile(
                    "st.async.shared::cluster.mbarrier::complete_tx::bytes.u32 [%0], %1, [%2];"
                    :: "r"(dst), "r"(__float_as_uint(hnew)), "r"(peerBar) : "memory");
            }
        }
        xpv = xpn;
        __syncthreads();   // local sH[nb] writes visible; sRed safe for reuse

        if (s + 1 < S_SZ) {
            // all threads wait for peer's half of h_next (parity = s & 1)
            uint32_t parity = (uint32_t)(s & 1);
            asm volatile(
                "{\n\t.reg .pred P;\n\t"
                "WL_%=:\n\t"
                "mbarrier.try_wait.parity.acquire.cluster.shared::cta.b64 P, [%0], %1, 0x989680;\n\t"
                "@!P bra WL_%=;\n\t}"
                :: "r"(barLocal), "r"(parity) : "memory");
        }
        sx += sstep;
    }
}

// ---------------------------------------------------------------------------
extern "C" void kernel_launch(void* const* d_in, const int* in_sizes, int n_in,
                              void* d_out, int out_size)
{
    const float* x    = (const float*)d_in[0];
    const float* Wx_f = (const float*)d_in[1];
    const float* Wh_f = (const float*)d_in[2];
    const float* b_f  = (const float*)d_in[3];
    const float* Wx_b = (const float*)d_in[4];
    const float* Wh_b = (const float*)d_in[5];
    const float* b_b  = (const float*)d_in[6];
    float* out = (float*)d_out;

    cudaFuncSetAttribute(xp_kernel, cudaFuncAttributeMaxDynamicSharedMemorySize,
                         XP_SMEM_FLOATS * 4);

    dim3 xpgrid(65536 / XP_ROWS, 2);
    xp_kernel<<<xpgrid, 256, XP_SMEM_FLOATS * 4>>>(x, Wx_f, b_f, Wx_b, b_b);
    rnn_kernel<<<128, 256>>>(Wh_f, Wh_b, out);
}

// round 14
// speedup vs baseline: 1.1078x; 1.0832x over previous
#include <cuda_runtime.h>
#include <cstdint>

// Bidirectional tanh-Elman RNN, B=32, S=2048, D=H=256, fp32.
//
// Phase 1 (xp_kernel): xp[dir] = x @ Wx_dir + b_dir  -> 128MB device scratch.
//   v2: 2-column x 32-row register blocking per thread (x-loads amortized
//   across 2 output columns), FFMA2 row-pairs. Bit-identical summation order
//   per output element to the previous version.
// Phase 2 (rnn_kernel): 64 clusters of 2 CTAs; cluster = one (dir, batch).
//   R7/R12 protocol VERBATIM (only passing protocol). Only change: tanhf ->
//   MUFU-based 1 - 2/(exp(2x)+1) to shorten the serial critical path.

#define S_SZ 2048
#define H_SZ 256
#define B_SZ 32

__device__ float g_xp[2u * 65536u * 256u];   // [dir][b*S + s][j]  128 MB scratch

__device__ __forceinline__ unsigned long long pack2(float a, float b) {
    unsigned long long r;
    asm("mov.b64 %0, {%1, %2};" : "=l"(r)
        : "r"(__float_as_uint(a)), "r"(__float_as_uint(b)));
    return r;
}
__device__ __forceinline__ void unpack2(unsigned long long p, float& a, float& b) {
    unsigned int lo, hi;
    asm("mov.b64 {%0, %1}, %2;" : "=r"(lo), "=r"(hi) : "l"(p));
    a = __uint_as_float(lo);
    b = __uint_as_float(hi);
}
__device__ __forceinline__ unsigned long long splat2(float a) {
    unsigned long long r;
    asm("mov.b64 %0, {%1, %1};" : "=l"(r) : "r"(__float_as_uint(a)));
    return r;
}
#define FMA2(acc, a, b) \
    asm("fma.rn.f32x2 %0, %1, %2, %0;" : "+l"(acc) : "l"(a), "l"(b))

// accurate-enough tanh off the MUFU pipes: abs err ~1e-7, handles +-inf ok
__device__ __forceinline__ float fast_tanh(float z) {
    float e = __expf(2.0f * z);
    return 1.0f - __fdividef(2.0f, e + 1.0f);
}

// ---------------------------------------------------------------------------
// Phase 1: input projection GEMM (fp32, FFMA2), rows = flattened (b, s)
//   CTA: 64 rows x 256 cols. Thread t: cols {jp, jp+128} (jp = t&127),
//   rows [rg*32, rg*32+32) (rg = t>>7).
// ---------------------------------------------------------------------------
#define XP_ROWS 64
#define XP_KC   64
#define XP_SMEM_FLOATS (XP_KC * 256 + XP_KC * 64)   // sW + sXT = 20480 floats

__global__ __launch_bounds__(256, 2) void xp_kernel(
    const float* __restrict__ x,
    const float* __restrict__ Wx_f, const float* __restrict__ b_f,
    const float* __restrict__ Wx_b, const float* __restrict__ b_b)
{
    extern __shared__ float sm[];
    float* sW  = sm;                 // [64][256]  sW[ii*256 + j]
    float* sXT = sm + XP_KC * 256;   // [64][64]   sXT[ii*64 + r]  (16B aligned)

    const int dir  = blockIdx.y;
    const int row0 = blockIdx.x * XP_ROWS;
    const float* W    = dir ? Wx_b : Wx_f;
    const float* bias = dir ? b_b  : b_f;
    const int t  = threadIdx.x;
    const int jp = t & 127;          // first output column
    const int rg = t >> 7;           // row group (32 rows)

    // 16 packed accumulators per column; pair p = rows (rg*32+2p, rg*32+2p+1)
    unsigned long long accA[16], accB[16];
    {
        unsigned long long ba = splat2(bias[jp]);
        unsigned long long bb = splat2(bias[jp + 128]);
        #pragma unroll
        for (int p = 0; p < 16; ++p) { accA[p] = ba; accB[p] = bb; }
    }

    for (int i0 = 0; i0 < H_SZ; i0 += XP_KC) {
        // stage W chunk [64 k][256 j] (coalesced)
        for (int idx = t; idx < XP_KC * 256; idx += 256)
            sW[idx] = W[(i0 + (idx >> 8)) * H_SZ + (idx & 255)];
        // stage x chunk transposed: sXT[k][r]
        {
            int r  = t >> 2;
            int iq = (t & 3) * 16;
            const float* xr = x + (size_t)(row0 + r) * H_SZ + i0 + iq;
            #pragma unroll
            for (int k = 0; k < 4; ++k) {
                float4 v = *(const float4*)(xr + k * 4);
                sXT[(iq + k*4 + 0) * 64 + r] = v.x;
                sXT[(iq + k*4 + 1) * 64 + r] = v.y;
                sXT[(iq + k*4 + 2) * 64 + r] = v.z;
                sXT[(iq + k*4 + 3) * 64 + r] = v.w;
            }
        }
        __syncthreads();
        for (int ii = 0; ii < XP_KC; ++ii) {
            unsigned long long wa = splat2(sW[ii * 256 + jp]);
            unsigned long long wb = splat2(sW[ii * 256 + jp + 128]);
            const ulonglong2* xv = (const ulonglong2*)(sXT + ii * 64 + rg * 32);
            #pragma unroll
            for (int q = 0; q < 8; ++q) {
                ulonglong2 v = xv[q];            // rows 4q..4q+3 (broadcast)
                FMA2(accA[2*q + 0], v.x, wa);
                FMA2(accA[2*q + 1], v.y, wa);
                FMA2(accB[2*q + 0], v.x, wb);
                FMA2(accB[2*q + 1], v.y, wb);
            }
        }
        __syncthreads();
    }
    float* dst = g_xp + ((size_t)dir * 65536u + row0 + rg * 32) * 256;
    #pragma unroll
    for (int p = 0; p < 16; ++p) {
        float a0, a1, b0, b1;
        unpack2(accA[p], a0, a1);
        unpack2(accB[p], b0, b1);
        dst[(size_t)(2*p + 0) * 256 + jp]       = a0;
        dst[(size_t)(2*p + 1) * 256 + jp]       = a1;
        dst[(size_t)(2*p + 0) * 256 + jp + 128] = b0;
        dst[(size_t)(2*p + 1) * 256 + jp + 128] = b1;
    }
}

// ---------------------------------------------------------------------------
// Phase 2: recurrence (R7/R12 protocol verbatim; FFMA2 dot; fast tanh).
// ---------------------------------------------------------------------------
__device__ __forceinline__ uint32_t smem_u32(const void* p) {
    uint32_t a;
    asm("{ .reg .u64 tmp; cvta.to.shared.u64 tmp, %1; cvt.u32.u64 %0, tmp; }"
        : "=r"(a) : "l"(p));
    return a;
}

__global__ __launch_bounds__(256, 1) __cluster_dims__(2, 1, 1)
void rnn_kernel(const float* __restrict__ Wh_f,
                const float* __restrict__ Wh_b,
                float* __restrict__ out)
{
    __shared__ __align__(16) float sH[2][H_SZ];   // full h vector, double-buffered
    __shared__ float sRed[128];                   // k-partials from kh=1
    __shared__ __align__(8) unsigned long long sBar;

    const int t     = threadIdx.x;
    const int rank  = blockIdx.x & 1;      // j-half owned by this CTA
    const int c     = blockIdx.x >> 1;
    const int dir   = c >> 5;
    const int b     = c & 31;
    const int kh    = t >> 7;
    const int jl    = t & 127;
    const int jglob = rank * 128 + jl;

    const float* Wh = dir ? Wh_b : Wh_f;

    // Wh[:, jglob] packed in register pairs
    unsigned long long w2[64];
    #pragma unroll
    for (int ii = 0; ii < 64; ++ii)
        w2[ii] = pack2(Wh[(kh * 128 + 2*ii + 0) * H_SZ + jglob],
                       Wh[(kh * 128 + 2*ii + 1) * H_SZ + jglob]);

    sH[0][t] = 0.0f;
    const uint32_t barLocal = smem_u32(&sBar);
    const uint32_t shBase   = smem_u32(&sH[0][0]);
    if (t == 0)
        asm volatile("mbarrier.init.shared.b64 [%0], %1;" :: "r"(barLocal), "r"(1) : "memory");
    __syncthreads();
    asm volatile("barrier.cluster.arrive.aligned;" ::: "memory");
    asm volatile("barrier.cluster.wait.aligned;"   ::: "memory");

    uint32_t peerBar, peerSh;
    {
        uint32_t pr = rank ^ 1;
        asm("mapa.shared::cluster.u32 %0, %1, %2;" : "=r"(peerBar) : "r"(barLocal), "r"(pr));
        asm("mapa.shared::cluster.u32 %0, %1, %2;" : "=r"(peerSh)  : "r"(shBase),   "r"(pr));
    }

    const float* xp_base  = g_xp + ((size_t)dir * 65536u + (size_t)b * S_SZ) * 256 + jglob;
    float*       out_base = out + (size_t)b * S_SZ * 512 + dir * 256 + jglob;

    int sx = dir ? (S_SZ - 1) : 0;
    const int sstep = dir ? -1 : 1;
    float xpv = (t < 128) ? __ldg(xp_base + (size_t)sx * 256) : 0.0f;

    for (int s = 0; s < S_SZ; ++s) {
        // one expect_tx per generation; safe: phase s-1 complete for every
        // thread (all threads passed the try_wait + __syncthreads below)
        if (t == 0 && s + 1 < S_SZ)
            asm volatile("mbarrier.arrive.expect_tx.shared.b64 _, [%0], %1;"
                         :: "r"(barLocal), "r"(512) : "memory");

        // prefetch next step's xp
        float xpn = 0.0f;
        if (t < 128 && s + 1 < S_SZ)
            xpn = __ldg(xp_base + (size_t)(sx + sstep) * 256);

        // partial GEMV over this thread's k-half (packed f32x2 FMA)
        const float* hb = sH[s & 1] + (kh << 7);
        unsigned long long p0 = 0ull, p1 = 0ull;
        #pragma unroll
        for (int q = 0; q < 32; ++q) {
            ulonglong2 hv = *(const ulonglong2*)(hb + (q << 2));  // broadcast
            FMA2(p0, hv.x, w2[2*q + 0]);
            FMA2(p1, hv.y, w2[2*q + 1]);
        }
        float a0, a1, a2, a3;
        unpack2(p0, a0, a1);
        unpack2(p1, a2, a3);
        float acc = (a0 + a1) + (a2 + a3);

        if (kh) sRed[jl] = acc;
        __syncthreads();

        if (t < 128) {
            float hnew = fast_tanh(acc + sRed[jl] + xpv);
            int nb = (s + 1) & 1;
            sH[nb][jglob] = hnew;                      // local copy
            out_base[(size_t)sx * 512] = hnew;         // output (coalesced)
            if (s + 1 < S_SZ) {
                uint32_t dst = peerSh + (uint32_t)(nb * 256 + jglob) * 4u;
                asm volatile(
                    "st.async.shared::cluster.mbarrier::complete_tx::bytes.u32 [%0], %1, [%2];"
                    :: "r"(dst), "r"(__float_as_uint(hnew)), "r"(peerBar) : "memory");
            }
        }
        xpv = xpn;
        __syncthreads();   // local sH[nb] writes visible; sRed safe for reuse

        if (s + 1 < S_SZ) {
            // all threads wait for peer's half of h_next (parity = s & 1)
            uint32_t parity = (uint32_t)(s & 1);
            asm volatile(
                "{\n\t.reg .pred P;\n\t"
                "WL_%=:\n\t"
                "mbarrier.try_wait.parity.acquire.cluster.shared::cta.b64 P, [%0], %1, 0x989680;\n\t"
                "@!P bra WL_%=;\n\t}"
                :: "r"(barLocal), "r"(parity) : "memory");
        }
        sx += sstep;
    }
}

// ---------------------------------------------------------------------------
extern "C" void kernel_launch(void* const* d_in, const int* in_sizes, int n_in,
                              void* d_out, int out_size)
{
    const float* x    = (const float*)d_in[0];
    const float* Wx_f = (const float*)d_in[1];
    const float* Wh_f = (const float*)d_in[2];
    const float* b_f  = (const float*)d_in[3];
    const float* Wx_b = (const float*)d_in[4];
    const float* Wh_b = (const float*)d_in[5];
    const float* b_b  = (const float*)d_in[6];
    float* out = (float*)d_out;

    cudaFuncSetAttribute(xp_kernel, cudaFuncAttributeMaxDynamicSharedMemorySize,
                         XP_SMEM_FLOATS * 4);

    dim3 xpgrid(65536 / XP_ROWS, 2);
    xp_kernel<<<xpgrid, 256, XP_SMEM_FLOATS * 4>>>(x, Wx_f, b_f, Wx_b, b_b);
    rnn_kernel<<<128, 256>>>(Wh_f, Wh_b, out);
}